// round 15
// baseline (speedup 1.0000x reference)
#include <cuda_runtime.h>
#include <cstdint>
#include <math.h>

// ---------------------------------------------------------------------------
// B=32, P=1024, HID=512, H=8, D=64, MEM=64, RANK=64
// coeffs[b,p,q] = sum_{i<16} F[b,p,i]*Hh[b,q,i] + Hh[b,q,16],  Hh = G.[F,1]
// 3 launches:
//   k1 (64 blocks):  Chebyshev node sums -> g_Fn, g_Gn          (NCH=16)
//   k2 (512 blocks): transform+Clenshaw+G (redundant, cheap ALU) +
//                    features + Hh -> g_F, g_Hh
//   k3 (4096 blocks): bilinear GEMM, B register-resident, streaming stores
// ---------------------------------------------------------------------------

#define Bx 32
#define Pn 1024
#define Hn 8
#define NCH 16

__device__ float g_Fn[Bx * NCH];
__device__ float g_Gn[Bx * NCH];
__device__ float g_F[(size_t)Bx * 16 * Pn];   // [b][i][p]
__device__ float g_Hh[(size_t)Bx * 17 * Pn];  // [b][i][p]

// ---------------------------------------------------------------------------
// Kernel 1: node sums. grid (2, 32), 512 thr.
// Block (c, b): nodes [c*8, c*8+8); warp w -> node w&7, p-half w>>3.
// ---------------------------------------------------------------------------
__global__ void __launch_bounds__(512) k1(
    const float* __restrict__ x,
    const float* __restrict__ w_k, const float* __restrict__ w_mem)
{
    const int tid = threadIdx.x;
    const int lane = tid & 31, wid = tid >> 5;
    const float PI = 3.14159265358979323846f;
    const int b = blockIdx.y;

    __shared__ __align__(16) float sx[Pn];
    __shared__ float sred[16];
    __shared__ float sAmax;
    __shared__ float sPd[2][8], sPn[2][8];

    sx[tid] = x[b * Pn + tid];
    sx[tid + 512] = x[b * Pn + tid + 512];

    // amax over all (h,m): thread computes its dot, block-reduce max|a|
    const int h8 = tid >> 6, m = tid & 63;
    float a = 0.f;
    #pragma unroll 8
    for (int d = 0; d < 64; d++)
        a = fmaf(w_k[h8 * 64 + d], w_mem[m * 64 + d], a);
    float am = fabsf(a);
    #pragma unroll
    for (int off = 16; off; off >>= 1)
        am = fmaxf(am, __shfl_down_sync(0xffffffffu, am, off));
    if (lane == 0) sred[wid] = am;
    __syncthreads();
    if (tid == 0) {
        float M = sred[0];
        #pragma unroll
        for (int i = 1; i < 16; i++) M = fmaxf(M, sred[i]);
        sAmax = M;
    }
    __syncthreads();

    // node for this warp
    const int nloc = wid & 7, half = wid >> 3;
    const int node = blockIdx.x * 8 + nloc;
    const float aj = sAmax * cosf((2 * node + 1) * (PI / (2 * NCH)));

    float num = 0.f, den = 0.f;
    const int pbase = half * 512;
    #pragma unroll 4
    for (int p = lane; p < 512; p += 32) {
        float xv = sx[pbase + p];
        float e = __expf(aj * xv);
        den += e;
        num = fmaf(xv, e, num);
    }
    #pragma unroll
    for (int off = 16; off; off >>= 1) {
        num += __shfl_down_sync(0xffffffffu, num, off);
        den += __shfl_down_sync(0xffffffffu, den, off);
    }
    if (lane == 0) { sPd[half][nloc] = den; sPn[half][nloc] = num; }
    __syncthreads();
    if (tid < 8) {
        g_Fn[b * NCH + blockIdx.x * 8 + tid] = sPd[0][tid] + sPd[1][tid];
        g_Gn[b * NCH + blockIdx.x * 8 + tid] = sPn[0][tid] + sPn[1][tid];
    }
}

// ---------------------------------------------------------------------------
// Kernel 2: finish stats + features + Hh. grid (16, 32), 512 thr, 64 p each.
// ---------------------------------------------------------------------------
__global__ void __launch_bounds__(512) k2(
    const float* __restrict__ x,
    const float* __restrict__ w_k, const float* __restrict__ w_mem,
    const float* __restrict__ w_u, const float* __restrict__ b_u,
    const float* __restrict__ w_v2, const float* __restrict__ b_v2,
    const float* __restrict__ w_v, const float* __restrict__ b_v,
    const float* __restrict__ w_q, const float* __restrict__ b_q)
{
    const int tid = threadIdx.x;
    const int lane = tid & 31, wid = tid >> 5;
    const float PI = 3.14159265358979323846f;
    const int b = blockIdx.y;
    const int p0 = blockIdx.x * 64;

    __shared__ __align__(16) float swq[512], sbq[512], swv[512], sbv[512];
    __shared__ float sWU[64][17];
    __shared__ float sWV[64][17];
    __shared__ float sG[289];
    __shared__ float sFn[NCH], sGn[NCH], scf[NCH], scg[NCH];
    __shared__ float sred[16];
    __shared__ float sAmax;
    __shared__ float sTm[512], sT2[512];
    __shared__ float sS1[8], sS2[8];
    __shared__ float sF[16][64];
    __shared__ float sxv[64];

    swq[tid] = w_q[tid]; sbq[tid] = b_q[tid];
    swv[tid] = w_v[tid]; sbv[tid] = b_v[tid];
    if (tid < NCH) { sFn[tid] = g_Fn[b * NCH + tid]; sGn[tid] = g_Gn[b * NCH + tid]; }
    if (tid < 64) sxv[tid] = x[b * Pn + p0 + tid];
    __syncthreads();

    // ---- G (redundant per block) ----
    for (int idx = tid; idx < 64 * 16; idx += 512) {
        int r = idx >> 4, i = idx & 15, hh = i & 7;
        const float* col = (i < 8) ? &swv[hh * 64] : &sbv[hh * 64];
        float su = 0.f, sv = 0.f;
        #pragma unroll 8
        for (int d = 0; d < 64; d++) {
            float c = col[d];
            su = fmaf(w_u[r * 512 + hh * 64 + d], c, su);
            sv = fmaf(w_v2[r * 512 + hh * 64 + d], c, sv);
        }
        sWU[r][i] = su;
        sWV[r][i] = sv;
    }
    if (tid < 64) { sWU[tid][16] = b_u[tid]; sWV[tid][16] = b_v2[tid]; }

    // ---- a[h,m] + amax ----
    const int h8 = tid >> 6, m = tid & 63;
    float a = 0.f;
    #pragma unroll 8
    for (int d = 0; d < 64; d++)
        a = fmaf(w_k[h8 * 64 + d], w_mem[m * 64 + d], a);
    float am = fabsf(a);
    #pragma unroll
    for (int off = 16; off; off >>= 1)
        am = fmaxf(am, __shfl_down_sync(0xffffffffu, am, off));
    if (lane == 0) sred[wid] = am;
    __syncthreads();
    if (tid == 0) {
        float M = sred[0];
        #pragma unroll
        for (int i = 1; i < 16; i++) M = fmaxf(M, sred[i]);
        sAmax = M;
    }

    // ---- G second stage ----
    __syncthreads();
    for (int idx = tid; idx < 289; idx += 512) {
        int i = idx / 17, j = idx % 17;
        float s = 0.f;
        #pragma unroll 8
        for (int r = 0; r < 64; r++)
            s = fmaf(sWU[r][i], sWV[r][j], s);
        sG[idx] = s;
    }

    // ---- coefficient transform ----
    if (tid < 2 * NCH) {
        const int k = tid & (NCH - 1);
        const float* src = (tid < NCH) ? sFn : sGn;
        float s = 0.f;
        #pragma unroll
        for (int j = 0; j < NCH; j++)
            s = fmaf((2.0f / NCH) * cosf(k * (2 * j + 1) * (PI / (2 * NCH))), src[j], s);
        if (tid < NCH) scf[k] = s; else scg[k] = s;
    }
    __syncthreads();

    // ---- Clenshaw -> T, S1/S2 ----
    {
        const float t = a / sAmax;
        const float t2 = 2.f * t;
        float c1 = 0.f, c2 = 0.f, d1 = 0.f, d2 = 0.f;
        #pragma unroll
        for (int k = NCH - 1; k >= 1; k--) {
            float nb = fmaf(t2, c1, -c2) + scf[k];
            c2 = c1; c1 = nb;
            float nd = fmaf(t2, d1, -d2) + scg[k];
            d2 = d1; d1 = nd;
        }
        const float f = fmaf(t, c1, -c2) + 0.5f * scf[0];
        const float g = fmaf(t, d1, -d2) + 0.5f * scg[0];
        const float T = g / f;
        sTm[tid] = T;
        sT2[tid] = T * T;
    }
    __syncthreads();
    if (wid < 8) {
        float s1 = sTm[wid * 64 + lane] + sTm[wid * 64 + 32 + lane];
        float s2 = sT2[wid * 64 + lane] + sT2[wid * 64 + 32 + lane];
        #pragma unroll
        for (int off = 16; off; off >>= 1) {
            s1 += __shfl_down_sync(0xffffffffu, s1, off);
            s2 += __shfl_down_sync(0xffffffffu, s2, off);
        }
        if (lane == 0) { sS1[wid] = s1; sS2[wid] = s2; }
    }
    __syncthreads();

    // ---- features for 64 p, thread=(h, pl) ----
    const int h = tid >> 6, pl = tid & 63;
    const float4* wq4 = (const float4*)&swq[h * 64];
    const float4* bq4 = (const float4*)&sbq[h * 64];
    const float4* wv4 = (const float4*)&swv[h * 64];
    const float4* bv4 = (const float4*)&sbv[h * 64];
    const float s1 = sS1[h], s2 = sS2[h];

    {
        const float xx = sxv[pl];
        float a1 = 0.f, a2 = 0.f;
        #pragma unroll
        for (int d4 = 0; d4 < 16; d4++) {
            float4 q = wq4[d4], bq = bq4[d4], wv = wv4[d4], bv = bv4[d4];
            float v, qf;
            v = fmaf(xx, q.x, bq.x); qf = (v > 0.f) ? (v + 1.f) : __expf(v);
            a1 = fmaf(qf, wv.x, a1); a2 = fmaf(qf, bv.x, a2);
            v = fmaf(xx, q.y, bq.y); qf = (v > 0.f) ? (v + 1.f) : __expf(v);
            a1 = fmaf(qf, wv.y, a1); a2 = fmaf(qf, bv.y, a2);
            v = fmaf(xx, q.z, bq.z); qf = (v > 0.f) ? (v + 1.f) : __expf(v);
            a1 = fmaf(qf, wv.z, a1); a2 = fmaf(qf, bv.z, a2);
            v = fmaf(xx, q.w, bq.w); qf = (v > 0.f) ? (v + 1.f) : __expf(v);
            a1 = fmaf(qf, wv.w, a1); a2 = fmaf(qf, bv.w, a2);
        }
        sF[h][pl]     = fmaf(a1, s2, a2 * s1);   // alpha
        sF[8 + h][pl] = fmaf(a1, s1, 64.f * a2); // beta
    }
    __syncthreads();

    // ---- write F and Hh ----
    {
        const size_t baseF = ((size_t)b * 16) * Pn + p0;
        #pragma unroll
        for (int r = 0; r < 2; r++) {
            int o = tid + r * 512;
            int i = o >> 6, pl2 = o & 63;
            g_F[baseF + (size_t)i * Pn + pl2] = sF[i][pl2];
        }
    }
    {
        const size_t baseH = ((size_t)b * 17) * Pn + p0;
        for (int o = tid; o < 17 * 64; o += 512) {
            int i = o >> 6, pl2 = o & 63;
            float s = sG[i * 17 + 16];
            #pragma unroll
            for (int j = 0; j < 16; j++)
                s = fmaf(sG[i * 17 + j], sF[j][pl2], s);
            g_Hh[baseH + (size_t)i * Pn + pl2] = s;
        }
    }
}

// ---------------------------------------------------------------------------
// Kernel 3: bilinear GEMM (R14 proven, ncu 38.6us). 256 thr, 64p x 128q tile,
// lane owns q-quad, B register-resident, streaming stores.
// ---------------------------------------------------------------------------
#define FMA2(acc64, a64, b64) \
    asm("fma.rn.f32x2 %0, %1, %2, %0;" : "+l"(acc64) : "l"(a64), "l"(b64))
#define UNPACK2(lo, hi, in64) do { \
    unsigned _u0, _u1; \
    asm("mov.b64 {%0, %1}, %2;" : "=r"(_u0), "=r"(_u1) : "l"(in64)); \
    lo = __uint_as_float(_u0); hi = __uint_as_float(_u1); } while (0)

__global__ void __launch_bounds__(256) kGemm(float* __restrict__ out)
{
    const int b = blockIdx.z;
    const int tq0 = blockIdx.x * 128;
    const int tp0 = blockIdx.y * 64;

    __shared__ __align__(16) float sFd[16][128];

    const int tid = threadIdx.x;
    const int lane = tid & 31, w = tid >> 5;
    const float* Fb = g_F + ((size_t)b * 16) * Pn;
    const float* HbQ = g_Hh + ((size_t)b * 17) * Pn + tq0 + 4 * lane;

    {
        int row = tid >> 4, c4 = (tid & 15) << 2;
        float4 v = *(const float4*)&Fb[(size_t)row * Pn + tp0 + c4];
        *(float4*)&sFd[row][c4 * 2]     = make_float4(v.x, v.x, v.y, v.y);
        *(float4*)&sFd[row][c4 * 2 + 4] = make_float4(v.z, v.z, v.w, v.w);
    }

    ulonglong2 hb = *(const ulonglong2*)&HbQ[(size_t)16 * Pn];
    unsigned long long bq[8][2];
    #pragma unroll
    for (int k = 0; k < 8; k++) {
        ulonglong2 v = *(const ulonglong2*)&HbQ[(size_t)k * Pn];
        bq[k][0] = v.x; bq[k][1] = v.y;
    }
    __syncthreads();

    unsigned long long acc[8][2];
    #pragma unroll
    for (int r = 0; r < 8; r++) { acc[r][0] = hb.x; acc[r][1] = hb.y; }

    const int rb2 = w * 16;

    #pragma unroll
    for (int k = 0; k < 8; k++) {
        const float* fr = &sFd[k][rb2];
        #pragma unroll
        for (int rp = 0; rp < 4; rp++) {
            ulonglong2 ad = *(const ulonglong2*)&fr[rp * 4];
            FMA2(acc[2 * rp][0],     ad.x, bq[k][0]);
            FMA2(acc[2 * rp][1],     ad.x, bq[k][1]);
            FMA2(acc[2 * rp + 1][0], ad.y, bq[k][0]);
            FMA2(acc[2 * rp + 1][1], ad.y, bq[k][1]);
        }
    }

    #pragma unroll
    for (int k = 0; k < 8; k++) {
        ulonglong2 v = *(const ulonglong2*)&HbQ[(size_t)(k + 8) * Pn];
        bq[k][0] = v.x; bq[k][1] = v.y;
    }
    #pragma unroll
    for (int k = 0; k < 8; k++) {
        const float* fr = &sFd[k + 8][rb2];
        #pragma unroll
        for (int rp = 0; rp < 4; rp++) {
            ulonglong2 ad = *(const ulonglong2*)&fr[rp * 4];
            FMA2(acc[2 * rp][0],     ad.x, bq[k][0]);
            FMA2(acc[2 * rp][1],     ad.x, bq[k][1]);
            FMA2(acc[2 * rp + 1][0], ad.y, bq[k][0]);
            FMA2(acc[2 * rp + 1][1], ad.y, bq[k][1]);
        }
    }

    float* outb = out + (size_t)b * Pn * Pn + (size_t)(tp0 + w * 8) * Pn + tq0 + 4 * lane;
    #pragma unroll
    for (int r = 0; r < 8; r++) {
        float4 v;
        UNPACK2(v.x, v.y, acc[r][0]);
        UNPACK2(v.z, v.w, acc[r][1]);
        __stcs((float4*)&outb[(size_t)r * Pn], v);
    }
}

// ---------------------------------------------------------------------------
// inputs: 0 x, 1 w_q, 2 b_q, 3 w_k, 4 b_k(unused), 5 w_v, 6 b_v, 7 w_mem,
//         8 w_u, 9 b_u, 10 w_v2, 11 b_v2
// ---------------------------------------------------------------------------
extern "C" void kernel_launch(void* const* d_in, const int* in_sizes, int n_in,
                              void* d_out, int out_size)
{
    const float* x    = (const float*)d_in[0];
    const float* w_q  = (const float*)d_in[1];
    const float* b_q  = (const float*)d_in[2];
    const float* w_k  = (const float*)d_in[3];
    const float* w_v  = (const float*)d_in[5];
    const float* b_v  = (const float*)d_in[6];
    const float* w_mem = (const float*)d_in[7];
    const float* w_u  = (const float*)d_in[8];
    const float* b_u  = (const float*)d_in[9];
    const float* w_v2 = (const float*)d_in[10];
    const float* b_v2 = (const float*)d_in[11];
    float* out = (float*)d_out;

    k1<<<dim3(2, Bx), 512>>>(x, w_k, w_mem);
    k2<<<dim3(16, Bx), 512>>>(x, w_k, w_mem, w_u, b_u, w_v2, b_v2,
                              w_v, b_v, w_q, b_q);
    kGemm<<<dim3(Pn / 128, Pn / 64, Bx), 256>>>(out);
}

// round 16
// speedup vs baseline: 2.9457x; 2.9457x over previous
#include <cuda_runtime.h>
#include <cstdint>
#include <math.h>

// ---------------------------------------------------------------------------
// B=32, P=1024, HID=512, H=8, D=64, MEM=64, RANK=64
// coeffs[b,p,q] = sum_{i<16} F[b,p,i]*Hh[b,q,i] + Hh[b,q,16],  Hh = G.[F,1]
// 3 launches (R11 structure, proven 101.4us):
//   kPre (33 blocks): per-batch Chebyshev stats (NCH=16) -> S1,S2; G matrix.
//   kFeat (512 blocks): features + Hh -> g_F, g_Hh.
//   kGemm (4096 blocks): bilinear GEMM v3, B register-resident, __stcs.
// ---------------------------------------------------------------------------

#define Bx 32
#define Pn 1024
#define Hn 8
#define NCH 16

__device__ float g_G[17 * 17];
__device__ float g_S1[Bx * Hn];
__device__ float g_S2[Bx * Hn];
__device__ float g_F[(size_t)Bx * 16 * Pn];   // [b][i][p]
__device__ float g_Hh[(size_t)Bx * 17 * Pn];  // [b][i][p]

// ---------------------------------------------------------------------------
// Kernel 1: prelude. blocks 0..31: per-batch Chebyshev stats -> S1,S2.
// block 32: 17x17 bilinear form G (computed ONCE; operands too big for smem).
// ---------------------------------------------------------------------------
__global__ void __launch_bounds__(512) kPre(
    const float* __restrict__ x,
    const float* __restrict__ w_k, const float* __restrict__ w_mem,
    const float* __restrict__ w_u, const float* __restrict__ b_u,
    const float* __restrict__ w_v2, const float* __restrict__ b_v2,
    const float* __restrict__ w_v, const float* __restrict__ b_v)
{
    const int tid = threadIdx.x;
    const int lane = tid & 31, wid = tid >> 5;
    const float PI = 3.14159265358979323846f;

    if (blockIdx.x == 32) {
        __shared__ float sWU[64][17];
        __shared__ float sWV[64][17];
        for (int idx = tid; idx < 64 * 16; idx += 512) {
            int r = idx >> 4, i = idx & 15, hh = i & 7;
            const float* col = (i < 8) ? w_v : b_v;
            float su = 0.f, sv = 0.f;
            #pragma unroll 8
            for (int d = 0; d < 64; d++) {
                float c = col[hh * 64 + d];
                su = fmaf(w_u[r * 512 + hh * 64 + d], c, su);
                sv = fmaf(w_v2[r * 512 + hh * 64 + d], c, sv);
            }
            sWU[r][i] = su;
            sWV[r][i] = sv;
        }
        if (tid < 64) { sWU[tid][16] = b_u[tid]; sWV[tid][16] = b_v2[tid]; }
        __syncthreads();
        for (int idx = tid; idx < 289; idx += 512) {
            int i = idx / 17, j = idx % 17;
            float s = 0.f;
            #pragma unroll 8
            for (int r = 0; r < 64; r++)
                s = fmaf(sWU[r][i], sWV[r][j], s);
            g_G[idx] = s;
        }
        return;
    }

    const int b = blockIdx.x;
    __shared__ __align__(16) float sx[Pn];
    __shared__ float sFn[NCH], sGn[NCH];
    __shared__ float scf[NCH], scg[NCH];
    __shared__ float sNodes[NCH];
    __shared__ float sred[16];
    __shared__ float sAmax;
    __shared__ float sTm[512], sT2[512];

    sx[tid] = x[b * Pn + tid];
    sx[tid + 512] = x[b * Pn + tid + 512];

    // a[h,m], thread = (h,m)  (w_k/w_mem small; L2-resident, 33 blocks only)
    const int h8 = tid >> 6, m = tid & 63;
    float a = 0.f;
    #pragma unroll 8
    for (int d = 0; d < 64; d++)
        a = fmaf(w_k[h8 * 64 + d], w_mem[m * 64 + d], a);

    float am = fabsf(a);
    #pragma unroll
    for (int off = 16; off; off >>= 1)
        am = fmaxf(am, __shfl_down_sync(0xffffffffu, am, off));
    if (lane == 0) sred[wid] = am;
    __syncthreads();
    if (tid == 0) {
        float M = sred[0];
        #pragma unroll
        for (int i = 1; i < 16; i++) M = fmaxf(M, sred[i]);
        sAmax = M;
    }
    __syncthreads();
    const float amax = sAmax;
    if (tid < NCH)
        sNodes[tid] = amax * cosf((2 * tid + 1) * (PI / (2 * NCH)));
    __syncthreads();

    // node sums: warp wid -> node wid (16 warps, 16 nodes, MUFU __expf)
    {
        const float aj = sNodes[wid];
        float num = 0.f, den = 0.f;
        #pragma unroll 8
        for (int p = lane; p < Pn; p += 32) {
            float xv = sx[p];
            float e = __expf(aj * xv);
            den += e;
            num = fmaf(xv, e, num);
        }
        #pragma unroll
        for (int off = 16; off; off >>= 1) {
            num += __shfl_down_sync(0xffffffffu, num, off);
            den += __shfl_down_sync(0xffffffffu, den, off);
        }
        if (lane == 0) { sFn[wid] = den; sGn[wid] = num; }
    }
    __syncthreads();

    // Chebyshev coefficient transform (threads 0..31)
    if (tid < 2 * NCH) {
        const int k = tid & (NCH - 1);
        const float* src = (tid < NCH) ? sFn : sGn;
        float s = 0.f;
        #pragma unroll
        for (int j = 0; j < NCH; j++)
            s = fmaf((2.0f / NCH) * cosf(k * (2 * j + 1) * (PI / (2 * NCH))), src[j], s);
        if (tid < NCH) scf[k] = s; else scg[k] = s;
    }
    __syncthreads();

    // Clenshaw -> T[h,m]
    {
        const float t = a / amax;
        const float t2 = 2.f * t;
        float c1 = 0.f, c2 = 0.f, d1 = 0.f, d2 = 0.f;
        #pragma unroll
        for (int k = NCH - 1; k >= 1; k--) {
            float nb = fmaf(t2, c1, -c2) + scf[k];
            c2 = c1; c1 = nb;
            float nd = fmaf(t2, d1, -d2) + scg[k];
            d2 = d1; d1 = nd;
        }
        const float f = fmaf(t, c1, -c2) + 0.5f * scf[0];
        const float g = fmaf(t, d1, -d2) + 0.5f * scg[0];
        const float T = g / f;
        sTm[tid] = T;
        sT2[tid] = T * T;
    }
    __syncthreads();
    if (wid < 8) {
        float s1 = sTm[wid * 64 + lane] + sTm[wid * 64 + 32 + lane];
        float s2 = sT2[wid * 64 + lane] + sT2[wid * 64 + 32 + lane];
        #pragma unroll
        for (int off = 16; off; off >>= 1) {
            s1 += __shfl_down_sync(0xffffffffu, s1, off);
            s2 += __shfl_down_sync(0xffffffffu, s2, off);
        }
        if (lane == 0) { g_S1[b * Hn + wid] = s1; g_S2[b * Hn + wid] = s2; }
    }
}

// ---------------------------------------------------------------------------
// Kernel 2: features (direct elu). grid (Pn/64, Bx) = 512 blocks, 512 thr.
// Writes g_F and g_Hh. (Byte-for-byte the R11 proven version.)
// ---------------------------------------------------------------------------
__global__ void __launch_bounds__(512) kFeat(
    const float* __restrict__ x,
    const float* __restrict__ w_q, const float* __restrict__ b_q,
    const float* __restrict__ w_v, const float* __restrict__ b_v)
{
    __shared__ __align__(16) float swq[512];
    __shared__ __align__(16) float sbq[512];
    __shared__ __align__(16) float swv[512];
    __shared__ __align__(16) float sbv[512];
    __shared__ float sG[289];
    __shared__ float sS1[8], sS2[8];
    __shared__ float sF[17][64];
    __shared__ float sxv[64];

    const int b = blockIdx.y, tid = threadIdx.x;
    const int p0 = blockIdx.x * 64;

    swq[tid] = w_q[tid]; sbq[tid] = b_q[tid];
    swv[tid] = w_v[tid]; sbv[tid] = b_v[tid];
    if (tid < 289) sG[tid] = g_G[tid];
    if (tid < 8) { sS1[tid] = g_S1[b * Hn + tid]; sS2[tid] = g_S2[b * Hn + tid]; }
    if (tid < 64) sxv[tid] = x[b * Pn + p0 + tid];
    __syncthreads();

    const int h = tid >> 6, pl = tid & 63;
    const float xv = sxv[pl];
    const float4* wq4 = (const float4*)&swq[h * 64];
    const float4* bq4 = (const float4*)&sbq[h * 64];
    const float4* wv4 = (const float4*)&swv[h * 64];
    const float4* bv4 = (const float4*)&sbv[h * 64];

    float a1 = 0.f, a2 = 0.f;
    #pragma unroll
    for (int d4 = 0; d4 < 16; d4++) {
        float4 q = wq4[d4], bq = bq4[d4], wv = wv4[d4], bv = bv4[d4];
        float v, qf;
        v = fmaf(xv, q.x, bq.x); qf = (v > 0.f) ? (v + 1.f) : __expf(v);
        a1 = fmaf(qf, wv.x, a1); a2 = fmaf(qf, bv.x, a2);
        v = fmaf(xv, q.y, bq.y); qf = (v > 0.f) ? (v + 1.f) : __expf(v);
        a1 = fmaf(qf, wv.y, a1); a2 = fmaf(qf, bv.y, a2);
        v = fmaf(xv, q.z, bq.z); qf = (v > 0.f) ? (v + 1.f) : __expf(v);
        a1 = fmaf(qf, wv.z, a1); a2 = fmaf(qf, bv.z, a2);
        v = fmaf(xv, q.w, bq.w); qf = (v > 0.f) ? (v + 1.f) : __expf(v);
        a1 = fmaf(qf, wv.w, a1); a2 = fmaf(qf, bv.w, a2);
    }
    const float s1 = sS1[h], s2 = sS2[h];
    sF[h][pl]     = fmaf(a1, s2, a2 * s1);   // alpha
    sF[8 + h][pl] = fmaf(a1, s1, 64.f * a2); // beta
    if (h == 0) sF[16][pl] = 1.f;
    __syncthreads();

    {
        size_t baseF = ((size_t)b * 16) * Pn + p0;
        int i = tid >> 6, pl2 = tid & 63;
        g_F[baseF + (size_t)i * Pn + pl2] = sF[i][pl2];
        g_F[baseF + (size_t)(i + 8) * Pn + pl2] = sF[i + 8][pl2];
    }
    {
        size_t baseH = ((size_t)b * 17) * Pn + p0;
        for (int o = tid; o < 17 * 64; o += 512) {
            int i = o >> 6, pl2 = o & 63;
            float s = 0.f;
            #pragma unroll
            for (int j = 0; j < 17; j++)
                s = fmaf(sG[i * 17 + j], sF[j][pl2], s);
            g_Hh[baseH + (size_t)i * Pn + pl2] = s;
        }
    }
}

// ---------------------------------------------------------------------------
// Kernel 3: bilinear GEMM v3 (R11 proven) + __stcs streaming stores.
// Block 256 thr, tile 64p x 128q; lane owns a q-quad; B register-resident.
// ---------------------------------------------------------------------------
#define FMA2(acc64, a64, b64) \
    asm("fma.rn.f32x2 %0, %1, %2, %0;" : "+l"(acc64) : "l"(a64), "l"(b64))
#define UNPACK2(lo, hi, in64) do { \
    unsigned _u0, _u1; \
    asm("mov.b64 {%0, %1}, %2;" : "=r"(_u0), "=r"(_u1) : "l"(in64)); \
    lo = __uint_as_float(_u0); hi = __uint_as_float(_u1); } while (0)

__global__ void __launch_bounds__(256) kGemm(float* __restrict__ out)
{
    const int b = blockIdx.z;
    const int tq0 = blockIdx.x * 128;
    const int tp0 = blockIdx.y * 64;

    __shared__ __align__(16) float sFd[16][128];  // 64 p, dup pairs

    const int tid = threadIdx.x;
    const int lane = tid & 31, w = tid >> 5;
    const float* Fb = g_F + ((size_t)b * 16) * Pn;
    const float* HbQ = g_Hh + ((size_t)b * 17) * Pn + tq0 + 4 * lane;

    {
        int row = tid >> 4, c4 = (tid & 15) << 2;
        float4 v = *(const float4*)&Fb[(size_t)row * Pn + tp0 + c4];
        *(float4*)&sFd[row][c4 * 2]     = make_float4(v.x, v.x, v.y, v.y);
        *(float4*)&sFd[row][c4 * 2 + 4] = make_float4(v.z, v.z, v.w, v.w);
    }

    ulonglong2 hb = *(const ulonglong2*)&HbQ[(size_t)16 * Pn];
    unsigned long long bq[8][2];
    #pragma unroll
    for (int k = 0; k < 8; k++) {
        ulonglong2 v = *(const ulonglong2*)&HbQ[(size_t)k * Pn];
        bq[k][0] = v.x; bq[k][1] = v.y;
    }
    __syncthreads();

    unsigned long long acc[8][2];
    #pragma unroll
    for (int r = 0; r < 8; r++) { acc[r][0] = hb.x; acc[r][1] = hb.y; }

    const int rb2 = w * 16;

    #pragma unroll
    for (int k = 0; k < 8; k++) {
        const float* fr = &sFd[k][rb2];
        #pragma unroll
        for (int rp = 0; rp < 4; rp++) {
            ulonglong2 ad = *(const ulonglong2*)&fr[rp * 4];
            FMA2(acc[2 * rp][0],     ad.x, bq[k][0]);
            FMA2(acc[2 * rp][1],     ad.x, bq[k][1]);
            FMA2(acc[2 * rp + 1][0], ad.y, bq[k][0]);
            FMA2(acc[2 * rp + 1][1], ad.y, bq[k][1]);
        }
    }

    #pragma unroll
    for (int k = 0; k < 8; k++) {
        ulonglong2 v = *(const ulonglong2*)&HbQ[(size_t)(k + 8) * Pn];
        bq[k][0] = v.x; bq[k][1] = v.y;
    }
    #pragma unroll
    for (int k = 0; k < 8; k++) {
        const float* fr = &sFd[k + 8][rb2];
        #pragma unroll
        for (int rp = 0; rp < 4; rp++) {
            ulonglong2 ad = *(const ulonglong2*)&fr[rp * 4];
            FMA2(acc[2 * rp][0],     ad.x, bq[k][0]);
            FMA2(acc[2 * rp][1],     ad.x, bq[k][1]);
            FMA2(acc[2 * rp + 1][0], ad.y, bq[k][0]);
            FMA2(acc[2 * rp + 1][1], ad.y, bq[k][1]);
        }
    }

    float* outb = out + (size_t)b * Pn * Pn + (size_t)(tp0 + w * 8) * Pn + tq0 + 4 * lane;
    #pragma unroll
    for (int r = 0; r < 8; r++) {
        float4 v;
        UNPACK2(v.x, v.y, acc[r][0]);
        UNPACK2(v.z, v.w, acc[r][1]);
        __stcs((float4*)&outb[(size_t)r * Pn], v);
    }
}

// ---------------------------------------------------------------------------
// inputs: 0 x, 1 w_q, 2 b_q, 3 w_k, 4 b_k(unused), 5 w_v, 6 b_v, 7 w_mem,
//         8 w_u, 9 b_u, 10 w_v2, 11 b_v2
// ---------------------------------------------------------------------------
extern "C" void kernel_launch(void* const* d_in, const int* in_sizes, int n_in,
                              void* d_out, int out_size)
{
    const float* x    = (const float*)d_in[0];
    const float* w_q  = (const float*)d_in[1];
    const float* b_q  = (const float*)d_in[2];
    const float* w_k  = (const float*)d_in[3];
    const float* w_v  = (const float*)d_in[5];
    const float* b_v  = (const float*)d_in[6];
    const float* w_mem = (const float*)d_in[7];
    const float* w_u  = (const float*)d_in[8];
    const float* b_u  = (const float*)d_in[9];
    const float* w_v2 = (const float*)d_in[10];
    const float* b_v2 = (const float*)d_in[11];
    float* out = (float*)d_out;

    kPre<<<33, 512>>>(x, w_k, w_mem, w_u, b_u, w_v2, b_v2, w_v, b_v);
    kFeat<<<dim3(Pn / 64, Bx), 512>>>(x, w_q, b_q, w_v, b_v);
    kGemm<<<dim3(Pn / 128, Pn / 64, Bx), 256>>>(out);
}